// round 6
// baseline (speedup 1.0000x reference)
#include <cuda_runtime.h>
#include <math.h>

// Problem shape (fixed by the benchmark reference)
#define NB 4
#define NG 1024
#define NT 1024
#define NK 5
#define NC 8
#define HROW (NK * NC)         // 40

// Tiling: 16 t-lanes x 8 channels = 128 threads; each thread owns 2 t's.
#define BLOCK 128
#define TL 16                  // t-lanes
#define T_TILE 32              // 2 t's per lane * 16 lanes
#define N_TTILES 32            // 32 * 32 = 1024 exactly
#define G_SPLIT 8
#define GH (NG / G_SPLIT)      // 128 g's staged per CTA
#define HT_STRIDE 6            // k-contiguous h row: 5 live + 1 pad (conflict-free banks)

// smem: uw (float2 per (g,c)) + transposed h
#define UW_F (2 * GH * NC)             // 2048 floats
#define HT_F (GH * NC * HT_STRIDE)     // 6144 floats
#define SMEM_BYTES ((UW_F + HT_F) * 4) // 32768 B -> 6.96 CTAs/SM (228KB), 1024-CTA single wave

#define NEG_HALF_LOG2E -0.72134752044448170f   // -0.5 * log2(e)

__device__ __forceinline__ float ex2f(float x) {
    float r; asm("ex2.approx.ftz.f32 %0, %1;" : "=f"(r) : "f"(x)); return r;
}

__global__ __launch_bounds__(BLOCK) void gauss_kernel(
    const float* __restrict__ x_grid,   // (b, g, c)
    const float* __restrict__ h_grid,   // (b, g, k, c)
    const float* __restrict__ target_x, // (b, t, c)
    const float* __restrict__ sigma,    // (k, c)
    float* __restrict__ out)            // (b, t, k, c)
{
    extern __shared__ float sm[];
    float* uw = sm;             // float2[(g,c)] = {u = m0*x^2, w = -2*m0*x}
    float* hT = uw + UW_F;      // [g][c][6] = {h_k0..h_k4, pad}

    const int gh   = blockIdx.x;    // g slice
    const int tile = blockIdx.y;    // t tile
    const int b    = blockIdx.z;    // batch
    const int tid  = threadIdx.x;
    const int c    = tid & (NC - 1);
    const int tl   = tid >> 3;

    // Per-channel exponent multipliers from sigma (base-2; matches exp(sigma)+EPS)
    float mk[NK];
    bool uni = true;
    #pragma unroll
    for (int k = 0; k < NK; ++k) {
        float s = expf(sigma[k * NC + c]) + 1e-6f;
        mk[k] = NEG_HALF_LOG2E / (s * s);
        if (k > 0) uni = uni && (mk[k] == mk[0]);
    }
    const float m0 = mk[0];

    // ---- Stage x -> (u, w). BLOCK % NC == 0 so (tid + r*BLOCK) & 7 == c always.
    {
        const float* xg = x_grid + ((size_t)b * NG + (size_t)gh * GH) * NC;
        #pragma unroll
        for (int r = 0; r < GH * NC / BLOCK; ++r) {   // 8 exact iters
            int i = tid + r * BLOCK;
            float x = xg[i];
            *(float2*)(uw + 2 * i) = make_float2(m0 * x * x, -2.0f * m0 * x);
        }
    }
    // ---- Stage h transposed: [g][k][c] gmem -> [g][c][6] smem. Shift/mask only.
    {
        const float* hg = h_grid + ((size_t)b * NG + (size_t)gh * GH) * HROW;
        #pragma unroll
        for (int r = 0; r < GH * NC / BLOCK; ++r) {   // 8 exact iters
            int idx = tid + r * BLOCK;                // (g, c) pair
            int g  = idx >> 3;
            int cc = idx & 7;
            const float* src = hg + g * HROW + cc;
            float h0 = src[0 * NC], h1 = src[1 * NC], h2 = src[2 * NC],
                  h3 = src[3 * NC], h4 = src[4 * NC];
            float* dst = hT + g * (NC * HT_STRIDE) + cc * HT_STRIDE;
            *(float2*)(dst + 0) = make_float2(h0, h1);
            *(float2*)(dst + 2) = make_float2(h2, h3);
            dst[4] = h4;
        }
    }
    __syncthreads();

    // 2 t's per thread: t = tile*32 + tl + {0,16}; always < 1024.
    const int t0 = tile * T_TILE + tl;
    const float* ty = target_x + ((size_t)b * NT + t0) * NC + c;
    const float y0 = ty[0];
    const float y1 = ty[TL * NC];

    float a0[NK] = {0,0,0,0,0};
    float a1[NK] = {0,0,0,0,0};

    const float2* uwc = (const float2*)uw + c;
    const float*  hb  = hT + c * HT_STRIDE;

    if (uni) {
        // Fast path: 1 ex2 per (g,t) serves all 5 k's; 2^(m0*y^2) factored out.
        #pragma unroll 4
        for (int g = 0; g < GH; ++g) {
            float2 p = uwc[g * NC];
            float e0 = ex2f(fmaf(p.y, y0, p.x));
            float e1 = ex2f(fmaf(p.y, y1, p.x));
            const float* hp = hb + g * (NC * HT_STRIDE);
            float2 hA = *(const float2*)(hp + 0);
            float2 hB = *(const float2*)(hp + 2);
            float  h4 = hp[4];
            a0[0] = fmaf(e0, hA.x, a0[0]);  a1[0] = fmaf(e1, hA.x, a1[0]);
            a0[1] = fmaf(e0, hA.y, a0[1]);  a1[1] = fmaf(e1, hA.y, a1[1]);
            a0[2] = fmaf(e0, hB.x, a0[2]);  a1[2] = fmaf(e1, hB.x, a1[2]);
            a0[3] = fmaf(e0, hB.y, a0[3]);  a1[3] = fmaf(e1, hB.y, a1[3]);
            a0[4] = fmaf(e0, h4,   a0[4]);  a1[4] = fmaf(e1, h4,   a1[4]);
        }
        const float s0 = ex2f(m0 * y0 * y0);
        const float s1 = ex2f(m0 * y1 * y1);
        float* o = out + ((size_t)b * NT + t0) * HROW + c;
        #pragma unroll
        for (int k = 0; k < NK; ++k) {
            atomicAdd(o + k * NC,             a0[k] * s0);
            atomicAdd(o + TL * HROW + k * NC, a1[k] * s1);
        }
    } else {
        // General path: per-k scales. q = m0*(x-y)^2 via +m0*y^2; rescale by mk/m0.
        float rk[NK];
        #pragma unroll
        for (int k = 0; k < NK; ++k) rk[k] = mk[k] / m0;
        const float r0 = m0 * y0 * y0;
        const float r1 = m0 * y1 * y1;
        #pragma unroll 2
        for (int g = 0; g < GH; ++g) {
            float2 p = uwc[g * NC];
            float q0 = fmaf(p.y, y0, p.x) + r0;
            float q1 = fmaf(p.y, y1, p.x) + r1;
            const float* hp = hb + g * (NC * HT_STRIDE);
            float2 hA = *(const float2*)(hp + 0);
            float2 hB = *(const float2*)(hp + 2);
            float  h4 = hp[4];
            float h[NK] = {hA.x, hA.y, hB.x, hB.y, h4};
            #pragma unroll
            for (int k = 0; k < NK; ++k) {
                a0[k] = fmaf(ex2f(q0 * rk[k]), h[k], a0[k]);
                a1[k] = fmaf(ex2f(q1 * rk[k]), h[k], a1[k]);
            }
        }
        float* o = out + ((size_t)b * NT + t0) * HROW + c;
        #pragma unroll
        for (int k = 0; k < NK; ++k) {
            atomicAdd(o + k * NC,             a0[k]);
            atomicAdd(o + TL * HROW + k * NC, a1[k]);
        }
    }
}

extern "C" void kernel_launch(void* const* d_in, const int* in_sizes, int n_in,
                              void* d_out, int out_size) {
    const float* x_grid  = (const float*)d_in[0];
    const float* h_grid  = (const float*)d_in[1];
    const float* target  = (const float*)d_in[2];
    const float* sigma   = (const float*)d_in[3];
    float* out = (float*)d_out;

    cudaFuncSetAttribute(gauss_kernel, cudaFuncAttributeMaxDynamicSharedMemorySize, SMEM_BYTES);

    cudaMemsetAsync(out, 0, (size_t)out_size * sizeof(float), 0);

    dim3 grid(G_SPLIT, N_TTILES, NB);   // 8 x 32 x 4 = 1024 CTAs, ~7/SM, single wave
    gauss_kernel<<<grid, BLOCK, SMEM_BYTES>>>(x_grid, h_grid, target, sigma, out);
}

// round 7
// speedup vs baseline: 1.0390x; 1.0390x over previous
#include <cuda_runtime.h>
#include <math.h>

// Problem shape (fixed by the benchmark reference)
#define NB 4
#define NG 1024
#define NT 1024
#define NK 5
#define NC 8
#define HROW (NK * NC)         // 40

// Tiling: 8 t-lanes x 8 channels = 64 threads; each thread owns 4 t's.
// Grid = G_SPLIT x N_TTILES x NB = 8*32*4 = 1024 CTAs -> 6.92/SM, balanced single wave.
#define BLOCK 64
#define TL 8                   // t-lanes
#define T_TILE 32              // 4 t's per lane * 8 lanes
#define N_TTILES 32            // 32 * 32 = 1024 exactly
#define G_SPLIT 8
#define GH (NG / G_SPLIT)      // 128 g's staged per CTA

// smem: uw (float2 per (g,c)) + h natural layout
#define UW_F (2 * GH * NC)     // 2048 floats
#define H_F  (GH * HROW)       // 5120 floats
#define SMEM_BYTES ((UW_F + H_F) * 4)   // 28672 B -> 7 CTAs/SM fits in 228KB

#define NEG_HALF_LOG2E -0.72134752044448170f   // -0.5 * log2(e)

__device__ __forceinline__ float ex2f(float x) {
    float r; asm("ex2.approx.ftz.f32 %0, %1;" : "=f"(r) : "f"(x)); return r;
}

__global__ __launch_bounds__(BLOCK) void gauss_kernel(
    const float* __restrict__ x_grid,   // (b, g, c)
    const float* __restrict__ h_grid,   // (b, g, k, c)
    const float* __restrict__ target_x, // (b, t, c)
    const float* __restrict__ sigma,    // (k, c)
    float* __restrict__ out)            // (b, t, k, c)
{
    extern __shared__ float sm[];
    float* uw = sm;             // float2[(g,c)] = {u = m0*x^2, w = -2*m0*x}
    float* hs = uw + UW_F;      // h natural [g][k][c]

    const int gh   = blockIdx.x;    // g slice
    const int tile = blockIdx.y;    // t tile
    const int b    = blockIdx.z;    // batch
    const int tid  = threadIdx.x;
    const int c    = tid & (NC - 1);
    const int tl   = tid >> 3;

    // Per-channel exponent multipliers from sigma (base-2; matches exp(sigma)+EPS)
    float mk[NK];
    bool uni = true;
    #pragma unroll
    for (int k = 0; k < NK; ++k) {
        float s = expf(sigma[k * NC + c]) + 1e-6f;
        mk[k] = NEG_HALF_LOG2E / (s * s);
        if (k > 0) uni = uni && (mk[k] == mk[0]);
    }
    const float m0 = mk[0];

    // ---- Stage x -> (u, w). BLOCK % NC == 0 so (tid + r*BLOCK) & 7 == c always:
    // each thread transforms elements of its own channel with its own m0.
    {
        const float* xg = x_grid + ((size_t)b * NG + (size_t)gh * GH) * NC;
        #pragma unroll
        for (int r = 0; r < GH * NC / BLOCK; ++r) {       // 16 exact iters
            int i = tid + r * BLOCK;
            float x = xg[i];
            *(float2*)(uw + 2 * i) = make_float2(m0 * x * x, -2.0f * m0 * x);
        }
    }
    // ---- Stage h: straight float4 copy, natural layout, no index math.
    {
        const float4* hg4 = (const float4*)(h_grid + ((size_t)b * NG + (size_t)gh * GH) * HROW);
        float4* hs4 = (float4*)hs;
        #pragma unroll
        for (int r = 0; r < H_F / 4 / BLOCK; ++r) {       // 20 exact iters
            int i = tid + r * BLOCK;
            hs4[i] = hg4[i];
        }
    }
    __syncthreads();

    // 4 t's per thread: t = tile*32 + tl + {0,8,16,24}; always < 1024.
    const int tbase = tile * T_TILE + tl;
    const float* ty = target_x + ((size_t)b * NT + tbase) * NC + c;
    const float y0 = ty[0 * TL * NC];
    const float y1 = ty[1 * TL * NC];
    const float y2 = ty[2 * TL * NC];
    const float y3 = ty[3 * TL * NC];

    float a0[NK] = {0,0,0,0,0};
    float a1[NK] = {0,0,0,0,0};
    float a2[NK] = {0,0,0,0,0};
    float a3[NK] = {0,0,0,0,0};

    const float2* uwc = (const float2*)uw + c;
    const float*  hc  = hs + c;

    if (uni) {
        // Fast path: 1 ex2 serves all 5 k's; 2^(m0*y^2) factored out of the g-sum.
        #pragma unroll 2
        for (int g = 0; g < GH; ++g) {
            float2 p = uwc[g * NC];
            float e0 = ex2f(fmaf(p.y, y0, p.x));
            float e1 = ex2f(fmaf(p.y, y1, p.x));
            float e2 = ex2f(fmaf(p.y, y2, p.x));
            float e3 = ex2f(fmaf(p.y, y3, p.x));
            const float* hp = hc + g * HROW;
            #pragma unroll
            for (int k = 0; k < NK; ++k) {
                float h = hp[k * NC];
                a0[k] = fmaf(e0, h, a0[k]);
                a1[k] = fmaf(e1, h, a1[k]);
                a2[k] = fmaf(e2, h, a2[k]);
                a3[k] = fmaf(e3, h, a3[k]);
            }
        }
        const float s0 = ex2f(m0 * y0 * y0);
        const float s1 = ex2f(m0 * y1 * y1);
        const float s2 = ex2f(m0 * y2 * y2);
        const float s3 = ex2f(m0 * y3 * y3);
        float* o = out + ((size_t)b * NT + tbase) * HROW + c;
        #pragma unroll
        for (int k = 0; k < NK; ++k) {
            atomicAdd(o + 0 * TL * HROW + k * NC, a0[k] * s0);
            atomicAdd(o + 1 * TL * HROW + k * NC, a1[k] * s1);
            atomicAdd(o + 2 * TL * HROW + k * NC, a2[k] * s2);
            atomicAdd(o + 3 * TL * HROW + k * NC, a3[k] * s3);
        }
    } else {
        // General path: per-k scales. q = m0*(x-y)^2 via +m0*y^2; rescale by mk/m0.
        float rk[NK];
        #pragma unroll
        for (int k = 0; k < NK; ++k) rk[k] = mk[k] / m0;
        const float r0 = m0 * y0 * y0;
        const float r1 = m0 * y1 * y1;
        const float r2 = m0 * y2 * y2;
        const float r3 = m0 * y3 * y3;
        for (int g = 0; g < GH; ++g) {
            float2 p = uwc[g * NC];
            float q0 = fmaf(p.y, y0, p.x) + r0;
            float q1 = fmaf(p.y, y1, p.x) + r1;
            float q2 = fmaf(p.y, y2, p.x) + r2;
            float q3 = fmaf(p.y, y3, p.x) + r3;
            const float* hp = hc + g * HROW;
            #pragma unroll
            for (int k = 0; k < NK; ++k) {
                float h = hp[k * NC];
                a0[k] = fmaf(ex2f(q0 * rk[k]), h, a0[k]);
                a1[k] = fmaf(ex2f(q1 * rk[k]), h, a1[k]);
                a2[k] = fmaf(ex2f(q2 * rk[k]), h, a2[k]);
                a3[k] = fmaf(ex2f(q3 * rk[k]), h, a3[k]);
            }
        }
        float* o = out + ((size_t)b * NT + tbase) * HROW + c;
        #pragma unroll
        for (int k = 0; k < NK; ++k) {
            atomicAdd(o + 0 * TL * HROW + k * NC, a0[k]);
            atomicAdd(o + 1 * TL * HROW + k * NC, a1[k]);
            atomicAdd(o + 2 * TL * HROW + k * NC, a2[k]);
            atomicAdd(o + 3 * TL * HROW + k * NC, a3[k]);
        }
    }
}

extern "C" void kernel_launch(void* const* d_in, const int* in_sizes, int n_in,
                              void* d_out, int out_size) {
    const float* x_grid  = (const float*)d_in[0];
    const float* h_grid  = (const float*)d_in[1];
    const float* target  = (const float*)d_in[2];
    const float* sigma   = (const float*)d_in[3];
    float* out = (float*)d_out;

    cudaFuncSetAttribute(gauss_kernel, cudaFuncAttributeMaxDynamicSharedMemorySize, SMEM_BYTES);

    cudaMemsetAsync(out, 0, (size_t)out_size * sizeof(float), 0);

    dim3 grid(G_SPLIT, N_TTILES, NB);   // 8 x 32 x 4 = 1024 CTAs, ~7/SM, balanced single wave
    gauss_kernel<<<grid, BLOCK, SMEM_BYTES>>>(x_grid, h_grid, target, sigma, out);
}

// round 8
// speedup vs baseline: 1.1748x; 1.1307x over previous
#include <cuda_runtime.h>
#include <math.h>

// Problem shape (fixed by the benchmark reference)
#define NB 4
#define NG 1024
#define NT 1024
#define NK 5
#define NC 8
#define HROW (NK * NC)         // 40

// Tiling: 16 t-lanes x 8 channels = 128 threads; each thread owns 4 t's.
// G_SPLIT=16 -> GH=64 -> smem 14336B -> 28 resident warps/SM (latency hiding x2 vs R5).
#define BLOCK 128
#define TL 16                  // t-lanes
#define T_TILE 64              // 4 t's per lane * 16 lanes
#define N_TTILES 16            // 16 * 64 = 1024 exactly
#define G_SPLIT 16
#define GH (NG / G_SPLIT)      // 64 g's staged per CTA

// smem: uw (float2 per (g,c)) + h natural layout
#define UW_F (2 * GH * NC)     // 1024 floats
#define H_F  (GH * HROW)       // 2560 floats
#define SMEM_BYTES ((UW_F + H_F) * 4)   // 14336 B

#define NEG_HALF_LOG2E -0.72134752044448170f   // -0.5 * log2(e)

__device__ __forceinline__ float ex2f(float x) {
    float r; asm("ex2.approx.ftz.f32 %0, %1;" : "=f"(r) : "f"(x)); return r;
}

__global__ __launch_bounds__(BLOCK) void gauss_kernel(
    const float* __restrict__ x_grid,   // (b, g, c)
    const float* __restrict__ h_grid,   // (b, g, k, c)
    const float* __restrict__ target_x, // (b, t, c)
    const float* __restrict__ sigma,    // (k, c)
    float* __restrict__ out)            // (b, t, k, c)
{
    extern __shared__ float sm[];
    float* uw = sm;             // float2[(g,c)] = {u = m0*x^2, w = -2*m0*x}
    float* hs = uw + UW_F;      // h natural [g][k][c]

    const int gh   = blockIdx.x;    // g slice
    const int tile = blockIdx.y;    // t tile
    const int b    = blockIdx.z;    // batch
    const int tid  = threadIdx.x;
    const int c    = tid & (NC - 1);
    const int tl   = tid >> 3;

    // Per-channel exponent multipliers from sigma (base-2; matches exp(sigma)+EPS)
    float mk[NK];
    bool uni = true;
    #pragma unroll
    for (int k = 0; k < NK; ++k) {
        float s = expf(sigma[k * NC + c]) + 1e-6f;
        mk[k] = NEG_HALF_LOG2E / (s * s);
        if (k > 0) uni = uni && (mk[k] == mk[0]);
    }
    const float m0 = mk[0];

    // ---- Stage x -> (u, w). BLOCK % NC == 0 so (tid + r*BLOCK) & 7 == c always:
    // each thread transforms elements of its own channel with its own m0.
    {
        const float* xg = x_grid + ((size_t)b * NG + (size_t)gh * GH) * NC;
        #pragma unroll
        for (int r = 0; r < GH * NC / BLOCK; ++r) {       // 4 exact iters
            int i = tid + r * BLOCK;
            float x = xg[i];
            *(float2*)(uw + 2 * i) = make_float2(m0 * x * x, -2.0f * m0 * x);
        }
    }
    // ---- Stage h: straight float4 copy, natural layout, no index math.
    {
        const float4* hg4 = (const float4*)(h_grid + ((size_t)b * NG + (size_t)gh * GH) * HROW);
        float4* hs4 = (float4*)hs;
        #pragma unroll
        for (int r = 0; r < H_F / 4 / BLOCK; ++r) {       // 5 exact iters
            int i = tid + r * BLOCK;
            hs4[i] = hg4[i];
        }
    }
    __syncthreads();

    // 4 t's per thread: t = tile*64 + tl + {0,16,32,48}; always < 1024.
    const int tbase = tile * T_TILE + tl;
    const float* ty = target_x + ((size_t)b * NT + tbase) * NC + c;
    const float y0 = ty[0 * TL * NC];
    const float y1 = ty[1 * TL * NC];
    const float y2 = ty[2 * TL * NC];
    const float y3 = ty[3 * TL * NC];

    float a0[NK] = {0,0,0,0,0};
    float a1[NK] = {0,0,0,0,0};
    float a2[NK] = {0,0,0,0,0};
    float a3[NK] = {0,0,0,0,0};

    const float2* uwc = (const float2*)uw + c;
    const float*  hc  = hs + c;

    if (uni) {
        // Fast path: 1 ex2 serves all 5 k's; 2^(m0*y^2) factored out of the g-sum.
        #pragma unroll 2
        for (int g = 0; g < GH; ++g) {
            float2 p = uwc[g * NC];
            float e0 = ex2f(fmaf(p.y, y0, p.x));
            float e1 = ex2f(fmaf(p.y, y1, p.x));
            float e2 = ex2f(fmaf(p.y, y2, p.x));
            float e3 = ex2f(fmaf(p.y, y3, p.x));
            const float* hp = hc + g * HROW;
            #pragma unroll
            for (int k = 0; k < NK; ++k) {
                float h = hp[k * NC];
                a0[k] = fmaf(e0, h, a0[k]);
                a1[k] = fmaf(e1, h, a1[k]);
                a2[k] = fmaf(e2, h, a2[k]);
                a3[k] = fmaf(e3, h, a3[k]);
            }
        }
        const float s0 = ex2f(m0 * y0 * y0);
        const float s1 = ex2f(m0 * y1 * y1);
        const float s2 = ex2f(m0 * y2 * y2);
        const float s3 = ex2f(m0 * y3 * y3);
        float* o = out + ((size_t)b * NT + tbase) * HROW + c;
        #pragma unroll
        for (int k = 0; k < NK; ++k) {
            atomicAdd(o + 0 * TL * HROW + k * NC, a0[k] * s0);
            atomicAdd(o + 1 * TL * HROW + k * NC, a1[k] * s1);
            atomicAdd(o + 2 * TL * HROW + k * NC, a2[k] * s2);
            atomicAdd(o + 3 * TL * HROW + k * NC, a3[k] * s3);
        }
    } else {
        // General path: per-k scales. q = m0*(x-y)^2 via +m0*y^2; rescale by mk/m0.
        float rk[NK];
        #pragma unroll
        for (int k = 0; k < NK; ++k) rk[k] = mk[k] / m0;
        const float r0 = m0 * y0 * y0;
        const float r1 = m0 * y1 * y1;
        const float r2 = m0 * y2 * y2;
        const float r3 = m0 * y3 * y3;
        for (int g = 0; g < GH; ++g) {
            float2 p = uwc[g * NC];
            float q0 = fmaf(p.y, y0, p.x) + r0;
            float q1 = fmaf(p.y, y1, p.x) + r1;
            float q2 = fmaf(p.y, y2, p.x) + r2;
            float q3 = fmaf(p.y, y3, p.x) + r3;
            const float* hp = hc + g * HROW;
            #pragma unroll
            for (int k = 0; k < NK; ++k) {
                float h = hp[k * NC];
                a0[k] = fmaf(ex2f(q0 * rk[k]), h, a0[k]);
                a1[k] = fmaf(ex2f(q1 * rk[k]), h, a1[k]);
                a2[k] = fmaf(ex2f(q2 * rk[k]), h, a2[k]);
                a3[k] = fmaf(ex2f(q3 * rk[k]), h, a3[k]);
            }
        }
        float* o = out + ((size_t)b * NT + tbase) * HROW + c;
        #pragma unroll
        for (int k = 0; k < NK; ++k) {
            atomicAdd(o + 0 * TL * HROW + k * NC, a0[k]);
            atomicAdd(o + 1 * TL * HROW + k * NC, a1[k]);
            atomicAdd(o + 2 * TL * HROW + k * NC, a2[k]);
            atomicAdd(o + 3 * TL * HROW + k * NC, a3[k]);
        }
    }
}

extern "C" void kernel_launch(void* const* d_in, const int* in_sizes, int n_in,
                              void* d_out, int out_size) {
    const float* x_grid  = (const float*)d_in[0];
    const float* h_grid  = (const float*)d_in[1];
    const float* target  = (const float*)d_in[2];
    const float* sigma   = (const float*)d_in[3];
    float* out = (float*)d_out;

    cudaFuncSetAttribute(gauss_kernel, cudaFuncAttributeMaxDynamicSharedMemorySize, SMEM_BYTES);

    cudaMemsetAsync(out, 0, (size_t)out_size * sizeof(float), 0);

    dim3 grid(G_SPLIT, N_TTILES, NB);   // 16 x 16 x 4 = 1024 CTAs x 4 warps -> 28 warps/SM
    gauss_kernel<<<grid, BLOCK, SMEM_BYTES>>>(x_grid, h_grid, target, sigma, out);
}